// round 1
// baseline (speedup 1.0000x reference)
#include <cuda_runtime.h>

// ---------------------------------------------------------------------------
// GNNBlock: 2-layer dense GAT (H=3, D1=D2=64) over 512 graphs x 128 nodes,
// fully-connected adjacency (incl. self loops), head-mean, lrelu(0.01),
// final sum pooling -> [512, 64].
// One CTA per graph; everything resident in SMEM. fp32 with f32x2 packed FMA.
// ---------------------------------------------------------------------------

typedef unsigned long long ull_t;

__device__ __forceinline__ ull_t pack2(float x, float y) {
    ull_t r;
    asm("mov.b64 %0, {%1, %2};" : "=l"(r) : "f"(x), "f"(y));
    return r;
}
__device__ __forceinline__ void fma2(ull_t& d, ull_t a, ull_t b) {
    asm("fma.rn.f32x2 %0, %1, %2, %0;" : "+l"(d) : "l"(a), "l"(b));
}
__device__ __forceinline__ float2 unpack2(ull_t v) {
    float x, y;
    asm("mov.b64 {%0, %1}, %2;" : "=f"(x), "=f"(y) : "l"(v));
    return make_float2(x, y);
}

static constexpr int NN   = 128;   // nodes per graph
static constexpr int HC   = 192;   // H * D = 3 * 64
static constexpr int WPAD = 132;   // padded stride for 128-col tiles (x / attn weights)
static constexpr int IPAD = 68;    // padded stride for layer-2 input (64 cols)

// SMEM layout (floats)
static constexpr int SH_OFF   = 0;                      // h features: 128 x 192
static constexpr int SW_OFF   = SH_OFF   + NN * HC;     // x tile / attn W: 128 x 132
static constexpr int SIN2_OFF = SW_OFF   + NN * WPAD;   // layer-2 input: 128 x 68
static constexpr int SB_OFF   = SIN2_OFF + NN * IPAD;   // W1/W2 staging: 2 x 8 x 192
static constexpr int SS_OFF   = SB_OFF   + 2 * 8 * HC;  // src scores: 3 x 128
static constexpr int SD_OFF   = SS_OFF   + 3 * NN;      // dst scores: 3 x 128
static constexpr int SF_OFF   = SD_OFF   + 3 * NN;      // final pool: 64
static constexpr int SMEM_FLOATS = SF_OFF + 64;         // 54080 floats = 216320 B

// ---------------------------------------------------------------------------
// GEMM: C[128 x 192] = A[128 x K] (smem, padded APAD) @ Bg[K x 192] (global)
// 512 threads: 32 (row groups of 4) x 16 (col groups of 12). B staged in smem
// 8-row chunks, double buffered. Accumulators packed f32x2 (4 rows x 6 pairs).
// ---------------------------------------------------------------------------
template <int K, int APAD>
__device__ __forceinline__ void gemm_to_sH(float* __restrict__ sH,
                                           const float* __restrict__ A,
                                           const float* __restrict__ Bg,
                                           float* __restrict__ sB, int tid) {
    const int ty = tid >> 4;        // 0..31
    const int tx = tid & 15;        // 0..15
    const int r0 = ty * 4;
    const int c0 = tx * 12;

    ull_t acc[4][6];
#pragma unroll
    for (int i = 0; i < 4; i++)
#pragma unroll
        for (int j = 0; j < 6; j++) acc[i][j] = 0ULL;

    constexpr int CH  = 8;          // k-rows per chunk
    constexpr int NCH = K / CH;

    // chunk 0 -> buffer 0
#pragma unroll
    for (int t = 0; t < 3; t++) sB[tid + 512 * t] = Bg[tid + 512 * t];
    __syncthreads();

    for (int ch = 0; ch < NCH; ch++) {
        float pre[3];
        const bool has_next = (ch + 1 < NCH);
        if (has_next) {
            const float* src = Bg + (ch + 1) * CH * HC;
#pragma unroll
            for (int t = 0; t < 3; t++) pre[t] = src[tid + 512 * t];
        }
        const float* Bs = sB + (ch & 1) * CH * HC;
        const int kb = ch * CH;
#pragma unroll
        for (int k4 = 0; k4 < CH; k4 += 4) {
            float4 a4[4];
#pragma unroll
            for (int i = 0; i < 4; i++)
                a4[i] = *reinterpret_cast<const float4*>(&A[(r0 + i) * APAD + kb + k4]);
#pragma unroll
            for (int kk = 0; kk < 4; kk++) {
                const float4* bp = reinterpret_cast<const float4*>(&Bs[(k4 + kk) * HC + c0]);
                const float4 x0 = bp[0], x1 = bp[1], x2 = bp[2];
                ull_t bv[6];
                bv[0] = pack2(x0.x, x0.y); bv[1] = pack2(x0.z, x0.w);
                bv[2] = pack2(x1.x, x1.y); bv[3] = pack2(x1.z, x1.w);
                bv[4] = pack2(x2.x, x2.y); bv[5] = pack2(x2.z, x2.w);
#pragma unroll
                for (int i = 0; i < 4; i++) {
                    const float a = reinterpret_cast<const float*>(&a4[i])[kk];
                    const ull_t av = pack2(a, a);
#pragma unroll
                    for (int j = 0; j < 6; j++) fma2(acc[i][j], av, bv[j]);
                }
            }
        }
        __syncthreads();                       // everyone done reading current buf
        if (has_next) {
            float* dst = sB + ((ch + 1) & 1) * CH * HC;
#pragma unroll
            for (int t = 0; t < 3; t++) dst[tid + 512 * t] = pre[t];
            __syncthreads();                   // next buf visible
        }
    }

    // store C tile (rows contiguous, vectorized)
#pragma unroll
    for (int i = 0; i < 4; i++) {
        float v[12];
#pragma unroll
        for (int j = 0; j < 6; j++) {
            const float2 f = unpack2(acc[i][j]);
            v[2 * j] = f.x; v[2 * j + 1] = f.y;
        }
        float4* cp = reinterpret_cast<float4*>(&sH[(r0 + i) * HC + c0]);
        cp[0] = make_float4(v[0], v[1], v[2],  v[3]);
        cp[1] = make_float4(v[4], v[5], v[6],  v[7]);
        cp[2] = make_float4(v[8], v[9], v[10], v[11]);
    }
}

// ---------------------------------------------------------------------------
// Per-node attention scores: s[h][n] = <h[n, h*64:...], att_src[h]>, same dst.
// ---------------------------------------------------------------------------
__device__ __forceinline__ void scores(const float* __restrict__ sH,
                                       const float* __restrict__ asrc,
                                       const float* __restrict__ adst,
                                       float* __restrict__ sS,
                                       float* __restrict__ sD, int tid) {
    const int w = tid >> 5, lane = tid & 31;
#pragma unroll
    for (int q = 0; q < 8; q++) {
        const int n = w * 8 + q;
#pragma unroll
        for (int h = 0; h < 3; h++) {
            const float2 hv = *reinterpret_cast<const float2*>(&sH[n * HC + h * 64 + 2 * lane]);
            const float2 av = *reinterpret_cast<const float2*>(&asrc[h * 64 + 2 * lane]);
            const float2 dv = *reinterpret_cast<const float2*>(&adst[h * 64 + 2 * lane]);
            float ps = hv.x * av.x + hv.y * av.y;
            float pd = hv.x * dv.x + hv.y * dv.y;
#pragma unroll
            for (int o = 16; o > 0; o >>= 1) {
                ps += __shfl_xor_sync(0xffffffffu, ps, o);
                pd += __shfl_xor_sync(0xffffffffu, pd, o);
            }
            if (lane == 0) { sS[h * NN + n] = ps; sD[h * NN + n] = pd; }
        }
    }
}

// ---------------------------------------------------------------------------
// Attention + aggregation. For each head: materialize normalized softmax
// weights W[i][j] in smem, then C[128x64] += W @ h_head (accumulators live in
// registers across all 3 heads). Epilogue: head-mean + bias + lrelu(0.01),
// then either store layer-2 input or reduce-sum rows into sF (final pool).
// ---------------------------------------------------------------------------
template <bool FINAL>
__device__ __forceinline__ void attention(const float* __restrict__ sH,
                                          const float* __restrict__ sS,
                                          const float* __restrict__ sD,
                                          float* __restrict__ sW,
                                          const float* __restrict__ bias,
                                          float* __restrict__ dst, int tid) {
    const int ty = tid >> 4, tx = tid & 15;
    const int r0 = ty * 4, c0 = tx * 4;
    const int w = tid >> 5, lane = tid & 31;

    ull_t acc[4][2];
#pragma unroll
    for (int i = 0; i < 4; i++) { acc[i][0] = 0ULL; acc[i][1] = 0ULL; }

    for (int h = 0; h < 3; h++) {
        // --- softmax row weights for rows [w*8, w*8+8) ---
#pragma unroll
        for (int q = 0; q < 8; q++) {
            const int i = w * 8 + q;
            const float di = sD[h * NN + i];
            float e0 = sS[h * NN + lane]      + di;
            float e1 = sS[h * NN + lane + 32] + di;
            float e2 = sS[h * NN + lane + 64] + di;
            float e3 = sS[h * NN + lane + 96] + di;
            e0 = (e0 >= 0.f) ? e0 : 0.2f * e0;
            e1 = (e1 >= 0.f) ? e1 : 0.2f * e1;
            e2 = (e2 >= 0.f) ? e2 : 0.2f * e2;
            e3 = (e3 >= 0.f) ? e3 : 0.2f * e3;
            float m = fmaxf(fmaxf(e0, e1), fmaxf(e2, e3));
#pragma unroll
            for (int o = 16; o > 0; o >>= 1)
                m = fmaxf(m, __shfl_xor_sync(0xffffffffu, m, o));
            e0 = __expf(e0 - m); e1 = __expf(e1 - m);
            e2 = __expf(e2 - m); e3 = __expf(e3 - m);
            float s = e0 + e1 + e2 + e3;
#pragma unroll
            for (int o = 16; o > 0; o >>= 1)
                s += __shfl_xor_sync(0xffffffffu, s, o);
            const float inv = __fdividef(1.f, s);
            sW[i * WPAD + lane]      = e0 * inv;
            sW[i * WPAD + lane + 32] = e1 * inv;
            sW[i * WPAD + lane + 64] = e2 * inv;
            sW[i * WPAD + lane + 96] = e3 * inv;
        }
        __syncthreads();

        // --- acc += W @ sH[:, h*64 + c0 : c0+4] ---
        const float* Bh = sH + h * 64 + c0;
        for (int k = 0; k < NN; k += 4) {
            float4 a4[4];
#pragma unroll
            for (int i = 0; i < 4; i++)
                a4[i] = *reinterpret_cast<const float4*>(&sW[(r0 + i) * WPAD + k]);
#pragma unroll
            for (int kk = 0; kk < 4; kk++) {
                const float4 b = *reinterpret_cast<const float4*>(&Bh[(k + kk) * HC]);
                const ull_t b0 = pack2(b.x, b.y);
                const ull_t b1 = pack2(b.z, b.w);
#pragma unroll
                for (int i = 0; i < 4; i++) {
                    const float a = reinterpret_cast<const float*>(&a4[i])[kk];
                    const ull_t av = pack2(a, a);
                    fma2(acc[i][0], av, b0);
                    fma2(acc[i][1], av, b1);
                }
            }
        }
        __syncthreads();   // before next head overwrites sW
    }

    const float third = 1.0f / 3.0f;
    const float bb0 = bias[c0], bb1 = bias[c0 + 1], bb2 = bias[c0 + 2], bb3 = bias[c0 + 3];

    if (!FINAL) {
#pragma unroll
        for (int i = 0; i < 4; i++) {
            const float2 f0 = unpack2(acc[i][0]);
            const float2 f1 = unpack2(acc[i][1]);
            float v0 = f0.x * third + bb0;
            float v1 = f0.y * third + bb1;
            float v2 = f1.x * third + bb2;
            float v3 = f1.y * third + bb3;
            v0 = (v0 >= 0.f) ? v0 : 0.01f * v0;
            v1 = (v1 >= 0.f) ? v1 : 0.01f * v1;
            v2 = (v2 >= 0.f) ? v2 : 0.01f * v2;
            v3 = (v3 >= 0.f) ? v3 : 0.01f * v3;
            float* dp = &dst[(r0 + i) * IPAD + c0];
            dp[0] = v0; dp[1] = v1; dp[2] = v2; dp[3] = v3;
        }
    } else {
        float p0 = 0.f, p1 = 0.f, p2 = 0.f, p3 = 0.f;
#pragma unroll
        for (int i = 0; i < 4; i++) {
            const float2 f0 = unpack2(acc[i][0]);
            const float2 f1 = unpack2(acc[i][1]);
            float v0 = f0.x * third + bb0;
            float v1 = f0.y * third + bb1;
            float v2 = f1.x * third + bb2;
            float v3 = f1.y * third + bb3;
            v0 = (v0 >= 0.f) ? v0 : 0.01f * v0;
            v1 = (v1 >= 0.f) ? v1 : 0.01f * v1;
            v2 = (v2 >= 0.f) ? v2 : 0.01f * v2;
            v3 = (v3 >= 0.f) ? v3 : 0.01f * v3;
            p0 += v0; p1 += v1; p2 += v2; p3 += v3;
        }
        // fold the two ty-halves of the warp (same c0 per tx)
        p0 += __shfl_xor_sync(0xffffffffu, p0, 16);
        p1 += __shfl_xor_sync(0xffffffffu, p1, 16);
        p2 += __shfl_xor_sync(0xffffffffu, p2, 16);
        p3 += __shfl_xor_sync(0xffffffffu, p3, 16);
        if (lane < 16) {
            atomicAdd(&dst[c0 + 0], p0);
            atomicAdd(&dst[c0 + 1], p1);
            atomicAdd(&dst[c0 + 2], p2);
            atomicAdd(&dst[c0 + 3], p3);
        }
    }
}

// ---------------------------------------------------------------------------
__global__ void __launch_bounds__(512, 1)
gat_fused_kernel(const float* __restrict__ x,
                 const float* __restrict__ W1, const float* __restrict__ as1,
                 const float* __restrict__ ad1, const float* __restrict__ b1,
                 const float* __restrict__ W2, const float* __restrict__ as2,
                 const float* __restrict__ ad2, const float* __restrict__ b2,
                 float* __restrict__ out) {
    extern __shared__ float sm[];
    float* sH   = sm + SH_OFF;
    float* sW   = sm + SW_OFF;
    float* sIn2 = sm + SIN2_OFF;
    float* sB   = sm + SB_OFF;
    float* sS   = sm + SS_OFF;
    float* sD   = sm + SD_OFF;
    float* sF   = sm + SF_OFF;

    const int g   = blockIdx.x;
    const int tid = threadIdx.x;

    // load x tile [128 x 128] into sW (padded stride WPAD), vectorized
    const float4* xg4 = reinterpret_cast<const float4*>(x + (size_t)g * (NN * 128));
#pragma unroll
    for (int t = 0; t < 8; t++) {
        const int idx4 = tid + t * 512;          // 0..4095
        const int r = idx4 >> 5;
        const int c = (idx4 & 31) * 4;
        *reinterpret_cast<float4*>(&sW[r * WPAD + c]) = xg4[idx4];
    }
    if (tid < 64) sF[tid] = 0.f;
    __syncthreads();

    // ---- layer 1 ----
    gemm_to_sH<128, WPAD>(sH, sW, W1, sB, tid);
    __syncthreads();
    scores(sH, as1, ad1, sS, sD, tid);
    __syncthreads();
    attention<false>(sH, sS, sD, sW, b1, sIn2, tid);
    __syncthreads();

    // ---- layer 2 ----
    gemm_to_sH<64, IPAD>(sH, sIn2, W2, sB, tid);
    __syncthreads();
    scores(sH, as2, ad2, sS, sD, tid);
    __syncthreads();
    attention<true>(sH, sS, sD, sW, b2, sF, tid);
    __syncthreads();

    if (tid < 64) out[g * 64 + tid] = sF[tid];
}

// ---------------------------------------------------------------------------
extern "C" void kernel_launch(void* const* d_in, const int* in_sizes, int n_in,
                              void* d_out, int out_size) {
    const float* x   = (const float*)d_in[0];
    // d_in[1] = batch_mask (int32): graphs are equal-sized & sorted -> identity layout
    const float* W1  = (const float*)d_in[2];
    const float* as1 = (const float*)d_in[3];
    const float* ad1 = (const float*)d_in[4];
    const float* b1  = (const float*)d_in[5];
    const float* W2  = (const float*)d_in[6];
    const float* as2 = (const float*)d_in[7];
    const float* ad2 = (const float*)d_in[8];
    const float* b2  = (const float*)d_in[9];
    float* out = (float*)d_out;

    const int B = in_sizes[0] / (128 * 128);   // 512 graphs

    const size_t smem_bytes = SMEM_FLOATS * sizeof(float);  // 216320 B
    cudaFuncSetAttribute(gat_fused_kernel,
                         cudaFuncAttributeMaxDynamicSharedMemorySize,
                         (int)smem_bytes);
    gat_fused_kernel<<<B, 512, smem_bytes>>>(x, W1, as1, ad1, b1,
                                             W2, as2, ad2, b2, out);
}

// round 2
// speedup vs baseline: 1.0459x; 1.0459x over previous
#include <cuda_runtime.h>

// ---------------------------------------------------------------------------
// GNNBlock: 2-layer dense GAT (H=3, D=64) over 512 graphs x 128 nodes, fully
// connected adjacency (+self loops), head-mean, lrelu(0.01), sum pool -> [512,64].
// One CTA per graph. All phases FMA-bound via f32x2 + warp-broadcast A operands
// + swizzled channel-major h for the aggregation GEMMs.
// ---------------------------------------------------------------------------

typedef unsigned long long ull_t;

__device__ __forceinline__ ull_t pack2(float x, float y) {
    ull_t r; asm("mov.b64 %0, {%1, %2};" : "=l"(r) : "f"(x), "f"(y)); return r;
}
__device__ __forceinline__ void fma2(ull_t& d, ull_t a, ull_t b) {
    asm("fma.rn.f32x2 %0, %1, %2, %0;" : "+l"(d) : "l"(a), "l"(b));
}
__device__ __forceinline__ float2 unpack2(ull_t v) {
    float x, y; asm("mov.b64 {%0, %1}, %2;" : "=f"(x), "=f"(y) : "l"(v));
    return make_float2(x, y);
}

static constexpr int NN  = 128;   // nodes per graph
static constexpr int HC  = 192;   // H * D
static constexpr int XP  = 128;   // row stride of x / P buffer (broadcast A: no pad)
static constexpr int X2P = 68;    // row stride of layer-2 input

// sHT: h transposed (channel-major), swizzled. Row c (0..191) x 128 floats.
// phys = c*128 + 4*((n/4) ^ (c&7)) + n%4  -> 32-lane column reads hit the
// 4-way LDS.128 throughput floor (optimal), no conflict penalty.
__device__ __forceinline__ int sht_off(int c, int n) {
    return c * 128 + (((((n) >> 2) ^ (c & 7)) << 2) | ((n) & 3));
}
__device__ __forceinline__ int sht_off4(int c, int n4) {   // n4 multiple of 4
    return c * 128 + ((((n4) >> 2) ^ (c & 7)) << 2);
}

// SMEM layout (floats)
static constexpr int SHT_OFF  = 0;                         // 192*128 = 24576
static constexpr int SW_OFF   = SHT_OFF  + HC * 128;       // x / P: 128*128
static constexpr int SX2_OFF  = SW_OFF   + NN * XP;        // 128*68
static constexpr int SB_OFF   = SX2_OFF  + NN * X2P;       // W staging 16*192
static constexpr int SS_OFF   = SB_OFF   + 16 * HC;        // 3*128 src scores
static constexpr int SD_OFF   = SS_OFF   + 3 * NN;         // 3*128 dst scores
static constexpr int SATT_OFF = SD_OFF   + 3 * NN;         // att vecs 2*192
static constexpr int SF_OFF   = SATT_OFF + 2 * HC;         // final pool 64
static constexpr int SMEM_FLOATS = SF_OFF + 64;            // 53952 fl = 215808 B

// ---------------------------------------------------------------------------
// GEMM: sHT (transposed, swizzled) <- A[128 x K] @ Bg[K x 192] (global).
// warp w owns rows [8w, 8w+8): A loads are warp-broadcast. lane owns 6 cols.
// Acc: f32x2 packed over N (8 rows x 3 col-pairs).
// ---------------------------------------------------------------------------
template <int K, int APAD>
__device__ __forceinline__ void gemm_transposed(float* __restrict__ sHT,
                                                const float* __restrict__ A,
                                                const float* __restrict__ Bg,
                                                float* __restrict__ sB, int tid) {
    const int warp = tid >> 5, lane = tid & 31;
    const int r0 = warp * 8, c0 = lane * 6;

    ull_t acc[8][3];
#pragma unroll
    for (int i = 0; i < 8; i++) { acc[i][0] = 0; acc[i][1] = 0; acc[i][2] = 0; }

    constexpr int CH  = 16;
    constexpr int NCH = K / CH;

    float pre[6];
#pragma unroll
    for (int t = 0; t < 6; t++) pre[t] = Bg[tid + 512 * t];

    for (int ch = 0; ch < NCH; ch++) {
        __syncthreads();                 // prior compute done reading sB
#pragma unroll
        for (int t = 0; t < 6; t++) sB[tid + 512 * t] = pre[t];
        __syncthreads();
        if (ch + 1 < NCH) {
            const float* src = Bg + (ch + 1) * CH * HC;
#pragma unroll
            for (int t = 0; t < 6; t++) pre[t] = src[tid + 512 * t];
        }
        const int kb = ch * CH;
#pragma unroll
        for (int k4 = 0; k4 < CH; k4 += 4) {
            float4 a4[8];
#pragma unroll
            for (int i = 0; i < 8; i++)
                a4[i] = *reinterpret_cast<const float4*>(&A[(r0 + i) * APAD + kb + k4]);
#pragma unroll
            for (int kk = 0; kk < 4; kk++) {
                const float* brow = &sB[(k4 + kk) * HC + c0];
                const ull_t b0 = *reinterpret_cast<const ull_t*>(brow);
                const ull_t b1 = *reinterpret_cast<const ull_t*>(brow + 2);
                const ull_t b2 = *reinterpret_cast<const ull_t*>(brow + 4);
#pragma unroll
                for (int i = 0; i < 8; i++) {
                    const float a = reinterpret_cast<const float*>(&a4[i])[kk];
                    const ull_t av = pack2(a, a);
                    fma2(acc[i][0], av, b0);
                    fma2(acc[i][1], av, b1);
                    fma2(acc[i][2], av, b2);
                }
            }
        }
    }

    // store transposed + swizzled: column vectors of 4 rows -> float4 STS
#pragma unroll
    for (int jj = 0; jj < 6; jj++) {
        const int c = c0 + jj;
        const int jp = jj >> 1;
        float4 v0, v1;
        if ((jj & 1) == 0) {
            v0 = make_float4(unpack2(acc[0][jp]).x, unpack2(acc[1][jp]).x,
                             unpack2(acc[2][jp]).x, unpack2(acc[3][jp]).x);
            v1 = make_float4(unpack2(acc[4][jp]).x, unpack2(acc[5][jp]).x,
                             unpack2(acc[6][jp]).x, unpack2(acc[7][jp]).x);
        } else {
            v0 = make_float4(unpack2(acc[0][jp]).y, unpack2(acc[1][jp]).y,
                             unpack2(acc[2][jp]).y, unpack2(acc[3][jp]).y);
            v1 = make_float4(unpack2(acc[4][jp]).y, unpack2(acc[5][jp]).y,
                             unpack2(acc[6][jp]).y, unpack2(acc[7][jp]).y);
        }
        *reinterpret_cast<float4*>(&sHT[sht_off4(c, r0)])     = v0;
        *reinterpret_cast<float4*>(&sHT[sht_off4(c, r0 + 4)]) = v1;
    }
}

// ---------------------------------------------------------------------------
// Scores: thread t<384 handles (node n, head h): dot of h-row with att vecs.
// ---------------------------------------------------------------------------
__device__ __forceinline__ void scores(const float* __restrict__ sHT,
                                       const float* __restrict__ sAtt,
                                       float* __restrict__ sS,
                                       float* __restrict__ sD, int tid) {
    if (tid < 384) {
        const int n = tid & 127, h = tid >> 7;
        const int nq = n >> 2, nr = n & 3;
        float ss = 0.f, dd = 0.f;
#pragma unroll 8
        for (int c = 0; c < 64; c++) {
            const int cr = h * 64 + c;
            const float hv = sHT[cr * 128 + (((nq ^ (cr & 7)) << 2) | nr)];
            ss += hv * sAtt[cr];
            dd += hv * sAtt[HC + cr];
        }
        sS[h * NN + n] = ss;
        sD[h * NN + n] = dd;
    }
}

// ---------------------------------------------------------------------------
// Attention: per head, softmax weights P -> sW, then C += P @ H_h using
// k-packed f32x2: rows 8/warp (broadcast A), cols {lane, lane+32}/thread.
// Accumulators persist across heads; epilogue = head-mean + bias + lrelu.
// ---------------------------------------------------------------------------
template <bool FINAL>
__device__ __forceinline__ void attention(const float* __restrict__ sHT,
                                          const float* __restrict__ sS,
                                          const float* __restrict__ sD,
                                          float* __restrict__ sW,
                                          const float* __restrict__ bias,
                                          float* __restrict__ dst, int tid) {
    const int warp = tid >> 5, lane = tid & 31;
    const int r0 = warp * 8;

    ull_t acc[8][2];
#pragma unroll
    for (int i = 0; i < 8; i++) { acc[i][0] = 0; acc[i][1] = 0; }

    for (int h = 0; h < 3; h++) {
        // softmax rows [8w, 8w+8)
#pragma unroll
        for (int q = 0; q < 8; q++) {
            const int i = r0 + q;
            const float di = sD[h * NN + i];
            float e0 = sS[h * NN + lane]      + di;
            float e1 = sS[h * NN + lane + 32] + di;
            float e2 = sS[h * NN + lane + 64] + di;
            float e3 = sS[h * NN + lane + 96] + di;
            e0 = (e0 >= 0.f) ? e0 : 0.2f * e0;
            e1 = (e1 >= 0.f) ? e1 : 0.2f * e1;
            e2 = (e2 >= 0.f) ? e2 : 0.2f * e2;
            e3 = (e3 >= 0.f) ? e3 : 0.2f * e3;
            float m = fmaxf(fmaxf(e0, e1), fmaxf(e2, e3));
#pragma unroll
            for (int o = 16; o > 0; o >>= 1)
                m = fmaxf(m, __shfl_xor_sync(0xffffffffu, m, o));
            e0 = __expf(e0 - m); e1 = __expf(e1 - m);
            e2 = __expf(e2 - m); e3 = __expf(e3 - m);
            float s = e0 + e1 + e2 + e3;
#pragma unroll
            for (int o = 16; o > 0; o >>= 1)
                s += __shfl_xor_sync(0xffffffffu, s, o);
            const float inv = __fdividef(1.f, s);
            sW[i * XP + lane]      = e0 * inv;
            sW[i * XP + lane + 32] = e1 * inv;
            sW[i * XP + lane + 64] = e2 * inv;
            sW[i * XP + lane + 96] = e3 * inv;
        }
        __syncthreads();

        // C[r0..r0+7][{lane, lane+32}] += P @ H_h   (k-packed f32x2)
        const int crA = h * 64 + lane;
        const int crB = crA + 32;
        const float* bAp = &sHT[crA * 128];
        const float* bBp = &sHT[crB * 128];
        const int xA = (crA & 7) << 2, xB = (crB & 7) << 2;
#pragma unroll 4
        for (int k4 = 0; k4 < NN; k4 += 4) {
            float4 a4[8];
#pragma unroll
            for (int i = 0; i < 8; i++)
                a4[i] = *reinterpret_cast<const float4*>(&sW[(r0 + i) * XP + k4]);
            const float4 b4A = *reinterpret_cast<const float4*>(bAp + (k4 ^ xA));
            const float4 b4B = *reinterpret_cast<const float4*>(bBp + (k4 ^ xB));
            const ull_t bA0 = reinterpret_cast<const ull_t*>(&b4A)[0];
            const ull_t bA1 = reinterpret_cast<const ull_t*>(&b4A)[1];
            const ull_t bB0 = reinterpret_cast<const ull_t*>(&b4B)[0];
            const ull_t bB1 = reinterpret_cast<const ull_t*>(&b4B)[1];
#pragma unroll
            for (int i = 0; i < 8; i++) {
                const ull_t a0 = reinterpret_cast<const ull_t*>(&a4[i])[0];
                const ull_t a1 = reinterpret_cast<const ull_t*>(&a4[i])[1];
                fma2(acc[i][0], a0, bA0);
                fma2(acc[i][0], a1, bA1);
                fma2(acc[i][1], a0, bB0);
                fma2(acc[i][1], a1, bB1);
            }
        }
        __syncthreads();   // before next head rewrites sW
    }

    const float third = 1.0f / 3.0f;
    const float bA = bias[lane], bB = bias[lane + 32];

    if (!FINAL) {
#pragma unroll
        for (int i = 0; i < 8; i++) {
            const float2 fA = unpack2(acc[i][0]);
            const float2 fB = unpack2(acc[i][1]);
            float vA = (fA.x + fA.y) * third + bA;
            float vB = (fB.x + fB.y) * third + bB;
            vA = (vA >= 0.f) ? vA : 0.01f * vA;
            vB = (vB >= 0.f) ? vB : 0.01f * vB;
            dst[(r0 + i) * X2P + lane]      = vA;
            dst[(r0 + i) * X2P + lane + 32] = vB;
        }
    } else {
        float pA = 0.f, pB = 0.f;
#pragma unroll
        for (int i = 0; i < 8; i++) {
            const float2 fA = unpack2(acc[i][0]);
            const float2 fB = unpack2(acc[i][1]);
            float vA = (fA.x + fA.y) * third + bA;
            float vB = (fB.x + fB.y) * third + bB;
            vA = (vA >= 0.f) ? vA : 0.01f * vA;
            vB = (vB >= 0.f) ? vB : 0.01f * vB;
            pA += vA; pB += vB;
        }
        atomicAdd(&dst[lane],      pA);
        atomicAdd(&dst[lane + 32], pB);
    }
}

// ---------------------------------------------------------------------------
__global__ void __launch_bounds__(512, 1)
gat_fused_kernel(const float* __restrict__ x,
                 const float* __restrict__ W1, const float* __restrict__ as1,
                 const float* __restrict__ ad1, const float* __restrict__ b1,
                 const float* __restrict__ W2, const float* __restrict__ as2,
                 const float* __restrict__ ad2, const float* __restrict__ b2,
                 float* __restrict__ out) {
    extern __shared__ float sm[];
    float* sHT  = sm + SHT_OFF;
    float* sW   = sm + SW_OFF;
    float* sX2  = sm + SX2_OFF;
    float* sB   = sm + SB_OFF;
    float* sS   = sm + SS_OFF;
    float* sD   = sm + SD_OFF;
    float* sAtt = sm + SATT_OFF;
    float* sF   = sm + SF_OFF;

    const int g   = blockIdx.x;
    const int tid = threadIdx.x;

    // x tile [128 x 128] -> sW (row-major, stride 128)
    const float4* xg4 = reinterpret_cast<const float4*>(x + (size_t)g * (NN * 128));
#pragma unroll
    for (int t = 0; t < 8; t++) {
        const int idx4 = tid + t * 512;
        const int r = idx4 >> 5;
        const int c4 = (idx4 & 31) << 2;
        *reinterpret_cast<float4*>(&sW[r * XP + c4]) = xg4[idx4];
    }
    if (tid < 64) sF[tid] = 0.f;
    if (tid < 384) sAtt[tid] = (tid < 192) ? as1[tid] : ad1[tid - 192];
    __syncthreads();

    // ---- layer 1 ----
    gemm_transposed<128, XP>(sHT, sW, W1, sB, tid);
    __syncthreads();
    scores(sHT, sAtt, sS, sD, tid);
    __syncthreads();
    attention<false>(sHT, sS, sD, sW, b1, sX2, tid);
    __syncthreads();

    // ---- layer 2 ----
    if (tid < 384) sAtt[tid] = (tid < 192) ? as2[tid] : ad2[tid - 192];
    gemm_transposed<64, X2P>(sHT, sX2, W2, sB, tid);
    __syncthreads();
    scores(sHT, sAtt, sS, sD, tid);
    __syncthreads();
    attention<true>(sHT, sS, sD, sW, b2, sF, tid);
    __syncthreads();

    if (tid < 64) out[g * 64 + tid] = sF[tid];
}

// ---------------------------------------------------------------------------
extern "C" void kernel_launch(void* const* d_in, const int* in_sizes, int n_in,
                              void* d_out, int out_size) {
    const float* x   = (const float*)d_in[0];
    // d_in[1] = batch_mask: equal-sized, sorted graphs -> identity layout
    const float* W1  = (const float*)d_in[2];
    const float* as1 = (const float*)d_in[3];
    const float* ad1 = (const float*)d_in[4];
    const float* b1  = (const float*)d_in[5];
    const float* W2  = (const float*)d_in[6];
    const float* as2 = (const float*)d_in[7];
    const float* ad2 = (const float*)d_in[8];
    const float* b2  = (const float*)d_in[9];
    float* out = (float*)d_out;

    const int B = in_sizes[0] / (128 * 128);

    const size_t smem_bytes = SMEM_FLOATS * sizeof(float);  // 215808 B
    cudaFuncSetAttribute(gat_fused_kernel,
                         cudaFuncAttributeMaxDynamicSharedMemorySize,
                         (int)smem_bytes);
    gat_fused_kernel<<<B, 512, smem_bytes>>>(x, W1, as1, ad1, b1,
                                             W2, as2, ad2, b2, out);
}

// round 4
// speedup vs baseline: 1.6619x; 1.5890x over previous
#include <cuda_runtime.h>
#include <cuda_bf16.h>

// ---------------------------------------------------------------------------
// GNNBlock via warp-level mma.sync bf16 split-precision (sm_103, no 'a' feats).
// One CTA per graph. A = Ah + Al, B = Bh + Bl (bf16); D = AhBh + AhBl + AlBh
// with fp32 accumulators -> ~2^-18 relative error.
// ---------------------------------------------------------------------------

typedef unsigned int uint_t;
typedef unsigned long long ull_t;

// ------------------------- smem byte offsets -------------------------------
#define OFF_AHI  0          // A operand hi: 128 rows x 136 bf16 (272 B)
#define OFF_ALO  34816
#define OFF_HTHI 69632      // H^T hi: 192 rows(ch) x 136 bf16 (272 B)
#define OFF_HTLO 121856
#define OFF_BST  174080     // W staging: 2 dbuf x (hi,lo) x 9216 B
#define OFF_SS   210944     // src scores 3x128 f32
#define OFF_SD   212480     // dst scores 3x128 f32
#define OFF_ATT  214016     // att vecs 2x192 f32
#define OFF_SF   215552     // final pool 64 f32
#define SMEM_BYTES 215808

#define BSTAGE   9216       // one staging buffer: 192 n x 24 bf16 (48 B rows)
#define HSTRIDE  136        // bf16 elems

__device__ __forceinline__ uint_t smem_u32(const void* p) {
    uint_t a;
    asm("{ .reg .u64 t; cvta.to.shared.u64 t, %1; cvt.u32.u64 %0, t; }"
        : "=r"(a) : "l"(p));
    return a;
}
__device__ __forceinline__ void ldsm4(uint_t r[4], uint_t addr) {
    asm volatile("ldmatrix.sync.aligned.m8n8.x4.shared.b16 {%0,%1,%2,%3}, [%4];"
        : "=r"(r[0]), "=r"(r[1]), "=r"(r[2]), "=r"(r[3]) : "r"(addr));
}
__device__ __forceinline__ void mma16816(float d[4], const uint_t a[4],
                                         uint_t b0, uint_t b1) {
    asm volatile("mma.sync.aligned.m16n8k16.row.col.f32.bf16.bf16.f32 "
        "{%0,%1,%2,%3}, {%4,%5,%6,%7}, {%8,%9}, {%0,%1,%2,%3};"
        : "+f"(d[0]), "+f"(d[1]), "+f"(d[2]), "+f"(d[3])
        : "r"(a[0]), "r"(a[1]), "r"(a[2]), "r"(a[3]), "r"(b0), "r"(b1));
}
__device__ __forceinline__ float bf16f(float v) {
    return __bfloat162float(__float2bfloat16(v));
}
// pack (lo, hi) in memory order
__device__ __forceinline__ uint_t pk2(float lo, float hi) {
    uint_t r;
    asm("cvt.rn.bf16x2.f32 %0, %1, %2;" : "=r"(r) : "f"(hi), "f"(lo));
    return r;
}

// ---------------------------------------------------------------------------
// GEMM: HT (transposed bf16 hi/lo) <- A[128 x 16*NCH] @ W[16*NCH x 192].
// Warp w: rows m0=(w&7)*16, col-half n0=(w>>3)*96 -> 12 m16n8 tiles.
// W streamed in 16-k chunks, double buffered, converted to [n][k] hi/lo.
// ---------------------------------------------------------------------------
template <int NCH>
__device__ __forceinline__ void gemm_layer(const float* __restrict__ Wg,
                                           char* smc, uint_t sbase, int tid) {
    const int warp = tid >> 5, lane = tid & 31;
    const int m0 = (warp & 7) * 16;
    const int n0 = (warp >> 3) * 96;

    float d[12][4];
#pragma unroll
    for (int p = 0; p < 12; p++)
#pragma unroll
        for (int q = 0; q < 4; q++) d[p][q] = 0.f;

    const uint_t aH = sbase + OFF_AHI + (m0 + (lane & 15)) * 272 + ((lane >> 4) << 4);
    const uint_t aL = aH + (OFF_ALO - OFF_AHI);
    const uint_t bRow = (n0 + (lane & 15)) * 48 + ((lane >> 4) << 4);

    float pre[6];
    {
        const float* wr = Wg + warp * 192;      // chunk 0: k = warp
#pragma unroll
        for (int p = 0; p < 6; p++) pre[p] = __ldg(&wr[lane + 32 * p]);
    }

    for (int ch = 0; ch < NCH; ch++) {
        __syncthreads();
        {
            __nv_bfloat16* bh = (__nv_bfloat16*)(smc + OFF_BST + (ch & 1) * (2 * BSTAGE));
            __nv_bfloat16* bl = bh + BSTAGE / 2;
#pragma unroll
            for (int p = 0; p < 6; p++) {
                const int n = lane + 32 * p;
                const float v = pre[p];
                const float hf = bf16f(v);
                bh[n * 24 + warp] = __float2bfloat16(hf);
                bl[n * 24 + warp] = __float2bfloat16(v - hf);
            }
        }
        __syncthreads();
        if (ch + 1 < NCH) {
            const float* wr = Wg + ((ch + 1) * 16 + warp) * 192;
#pragma unroll
            for (int p = 0; p < 6; p++) pre[p] = __ldg(&wr[lane + 32 * p]);
        }
        uint_t ah[4], al[4];
        ldsm4(ah, aH + ch * 32);
        ldsm4(al, aL + ch * 32);
        const uint_t bH = sbase + OFF_BST + (ch & 1) * (2 * BSTAGE) + bRow;
        const uint_t bL = bH + BSTAGE;
#pragma unroll
        for (int p = 0; p < 6; p++) {
            uint_t bh[4], bl[4];
            ldsm4(bh, bH + p * (16 * 48));
            ldsm4(bl, bL + p * (16 * 48));
            mma16816(d[2 * p],     ah, bh[0], bh[2]);
            mma16816(d[2 * p + 1], ah, bh[1], bh[3]);
            mma16816(d[2 * p],     ah, bl[0], bl[2]);
            mma16816(d[2 * p + 1], ah, bl[1], bl[3]);
            mma16816(d[2 * p],     al, bh[0], bh[2]);
            mma16816(d[2 * p + 1], al, bh[1], bh[3]);
        }
    }

    // store H^T (hi/lo): element (node r, ch c) -> HT[c][r]
    const int g = lane >> 2, tg = lane & 3;
    __nv_bfloat16* Hh = (__nv_bfloat16*)(smc + OFF_HTHI);
    __nv_bfloat16* Hl = (__nv_bfloat16*)(smc + OFF_HTLO);
#pragma unroll
    for (int p = 0; p < 12; p++) {
        const int c = n0 + 8 * p + 2 * tg;
        const int r = m0 + g;
#pragma unroll
        for (int q = 0; q < 4; q++) {
            const int cc = c + (q & 1);
            const int rr = r + ((q >> 1) << 3);
            const float v = d[p][q];
            const float hf = bf16f(v);
            Hh[cc * HSTRIDE + rr] = __float2bfloat16(hf);
            Hl[cc * HSTRIDE + rr] = __float2bfloat16(v - hf);
        }
    }
}

// ---------------------------------------------------------------------------
// Scores: thread t<384 handles (node n, head h): dot over 64 channels.
// ---------------------------------------------------------------------------
__device__ __forceinline__ void scores_phase(char* smc, int tid) {
    if (tid >= 384) return;
    const int n = tid & 127, h = tid >> 7;
    const __nv_bfloat16* Hh = (const __nv_bfloat16*)(smc + OFF_HTHI);
    const __nv_bfloat16* Hl = (const __nv_bfloat16*)(smc + OFF_HTLO);
    const float* As = (const float*)(smc + OFF_ATT) + h * 64;
    const float* Ad = (const float*)(smc + OFF_ATT) + 192 + h * 64;
    float ss = 0.f, dd = 0.f;
#pragma unroll 8
    for (int c = 0; c < 64; c++) {
        const int cr = h * 64 + c;
        const float hv = __bfloat162float(Hh[cr * HSTRIDE + n]) +
                         __bfloat162float(Hl[cr * HSTRIDE + n]);
        ss += hv * As[c];
        dd += hv * Ad[c];
    }
    ((float*)(smc + OFF_SS))[h * 128 + n] = ss;
    ((float*)(smc + OFF_SD))[h * 128 + n] = dd;
}

// ---------------------------------------------------------------------------
// Softmax for head h: rows [8*warp, 8*warp+8) -> P hi/lo into A buffers.
// ---------------------------------------------------------------------------
__device__ __forceinline__ void softmax_head(char* smc, int h, int tid) {
    const int warp = tid >> 5, lane = tid & 31;
    const float* Ss = (const float*)(smc + OFF_SS) + h * 128;
    const float* Sd = (const float*)(smc + OFF_SD) + h * 128;
    ull_t* Ah = (ull_t*)(smc + OFF_AHI);
    ull_t* Al = (ull_t*)(smc + OFF_ALO);
    const float4 s4 = *(const float4*)(Ss + lane * 4);
#pragma unroll 1
    for (int q = 0; q < 8; q++) {
        const int i = warp * 8 + q;
        const float di = Sd[i];
        float e0 = s4.x + di, e1 = s4.y + di, e2 = s4.z + di, e3 = s4.w + di;
        e0 = (e0 >= 0.f) ? e0 : 0.2f * e0;
        e1 = (e1 >= 0.f) ? e1 : 0.2f * e1;
        e2 = (e2 >= 0.f) ? e2 : 0.2f * e2;
        e3 = (e3 >= 0.f) ? e3 : 0.2f * e3;
        float m = fmaxf(fmaxf(e0, e1), fmaxf(e2, e3));
#pragma unroll
        for (int o = 16; o > 0; o >>= 1)
            m = fmaxf(m, __shfl_xor_sync(0xffffffffu, m, o));
        e0 = __expf(e0 - m); e1 = __expf(e1 - m);
        e2 = __expf(e2 - m); e3 = __expf(e3 - m);
        float sum = e0 + e1 + e2 + e3;
#pragma unroll
        for (int o = 16; o > 0; o >>= 1)
            sum += __shfl_xor_sync(0xffffffffu, sum, o);
        const float inv = __fdividef(1.f, sum);
        e0 *= inv; e1 *= inv; e2 *= inv; e3 *= inv;
        const float h0 = bf16f(e0), h1 = bf16f(e1), h2 = bf16f(e2), h3 = bf16f(e3);
        Ah[i * 34 + lane] = (ull_t)pk2(h0, h1) | ((ull_t)pk2(h2, h3) << 32);
        Al[i * 34 + lane] = (ull_t)pk2(e0 - h0, e1 - h1)
                          | ((ull_t)pk2(e2 - h2, e3 - h3) << 32);
    }
}

// ---------------------------------------------------------------------------
// Aggregation head h: dA += P @ H_h. A = P (A bufs), B = HT rows [64h, 64h+64).
// Warp w: rows m0=(w&7)*16, cols c0=(w>>3)*32 -> 4 m16n8 tiles, K=128.
// ---------------------------------------------------------------------------
__device__ __forceinline__ void aggregate_head(float dA[4][4], char* smc,
                                               uint_t sbase, int h, int tid) {
    const int warp = tid >> 5, lane = tid & 31;
    const int m0 = (warp & 7) * 16;
    const int c0 = (warp >> 3) * 32;
    const uint_t aH = sbase + OFF_AHI + (m0 + (lane & 15)) * 272 + ((lane >> 4) << 4);
    const uint_t aL = aH + (OFF_ALO - OFF_AHI);
    const uint_t bH = sbase + OFF_HTHI + (h * 64 + c0 + (lane & 15)) * 272
                    + ((lane >> 4) << 4);
    const uint_t bL = bH + (OFF_HTLO - OFF_HTHI);
#pragma unroll
    for (int s = 0; s < 8; s++) {
        uint_t ah[4], al[4];
        ldsm4(ah, aH + s * 32);
        ldsm4(al, aL + s * 32);
#pragma unroll
        for (int p = 0; p < 2; p++) {
            uint_t bh[4], bl[4];
            ldsm4(bh, bH + p * (16 * 272) + s * 32);
            ldsm4(bl, bL + p * (16 * 272) + s * 32);
            mma16816(dA[2 * p],     ah, bh[0], bh[2]);
            mma16816(dA[2 * p + 1], ah, bh[1], bh[3]);
            mma16816(dA[2 * p],     ah, bl[0], bl[2]);
            mma16816(dA[2 * p + 1], ah, bl[1], bl[3]);
            mma16816(dA[2 * p],     al, bh[0], bh[2]);
            mma16816(dA[2 * p + 1], al, bh[1], bh[3]);
        }
    }
}

// ---------------------------------------------------------------------------
__global__ void __launch_bounds__(512, 1)
gat_mma_kernel(const float* __restrict__ x,
               const float* __restrict__ W1, const float* __restrict__ as1,
               const float* __restrict__ ad1, const float* __restrict__ b1,
               const float* __restrict__ W2, const float* __restrict__ as2,
               const float* __restrict__ ad2, const float* __restrict__ b2,
               float* __restrict__ out) {
    extern __shared__ char smc[];
    const uint_t sbase = smem_u32(smc);
    const int tid = threadIdx.x;
    const int warp = tid >> 5, lane = tid & 31;

    float* sAtt = (float*)(smc + OFF_ATT);
    float* sF   = (float*)(smc + OFF_SF);

    // ---- prologue: X [128x128] f32 -> A hi/lo ----
    {
        const float4* xg4 = (const float4*)(x + (size_t)blockIdx.x * (128 * 128));
        ull_t* Ah = (ull_t*)(smc + OFF_AHI);
        ull_t* Al = (ull_t*)(smc + OFF_ALO);
#pragma unroll
        for (int t = 0; t < 8; t++) {
            const int idx4 = tid + 512 * t;
            const int row = idx4 >> 5, col4 = idx4 & 31;
            const float4 v = xg4[idx4];
            const float h0 = bf16f(v.x), h1 = bf16f(v.y);
            const float h2 = bf16f(v.z), h3 = bf16f(v.w);
            Ah[row * 34 + col4] = (ull_t)pk2(h0, h1) | ((ull_t)pk2(h2, h3) << 32);
            Al[row * 34 + col4] = (ull_t)pk2(v.x - h0, v.y - h1)
                                | ((ull_t)pk2(v.z - h2, v.w - h3) << 32);
        }
    }
    if (tid < 384) sAtt[tid] = (tid < 192) ? __ldg(&as1[tid]) : __ldg(&ad1[tid - 192]);
    if (tid < 64) sF[tid] = 0.f;
    // gemm's first __syncthreads orders these before any read

    float dA[4][4];

    // ================= layer 1 =================
    gemm_layer<8>(W1, smc, sbase, tid);
    __syncthreads();
    scores_phase(smc, tid);
    __syncthreads();

#pragma unroll
    for (int p = 0; p < 4; p++)
#pragma unroll
        for (int q = 0; q < 4; q++) dA[p][q] = 0.f;

    for (int h = 0; h < 3; h++) {
        softmax_head(smc, h, tid);
        __syncthreads();
        aggregate_head(dA, smc, sbase, h, tid);
        __syncthreads();
    }

    // epilogue 1: head-mean + bias + lrelu -> X2 into A hi/lo (cols 0..63)
    {
        const int m0 = (warp & 7) * 16;
        const int c0 = (warp >> 3) * 32;
        const int g = lane >> 2, tg = lane & 3;
        uint_t* Ah = (uint_t*)(smc + OFF_AHI);
        uint_t* Al = (uint_t*)(smc + OFF_ALO);
#pragma unroll
        for (int p = 0; p < 4; p++) {
            const int chn = c0 + 8 * p + 2 * tg;
            const float bb0 = __ldg(&b1[chn]), bb1 = __ldg(&b1[chn + 1]);
            float v0 = dA[p][0] * (1.f / 3.f) + bb0;
            float v1 = dA[p][1] * (1.f / 3.f) + bb1;
            float v2 = dA[p][2] * (1.f / 3.f) + bb0;
            float v3 = dA[p][3] * (1.f / 3.f) + bb1;
            v0 = (v0 >= 0.f) ? v0 : 0.01f * v0;
            v1 = (v1 >= 0.f) ? v1 : 0.01f * v1;
            v2 = (v2 >= 0.f) ? v2 : 0.01f * v2;
            v3 = (v3 >= 0.f) ? v3 : 0.01f * v3;
            const float h0 = bf16f(v0), h1 = bf16f(v1);
            const float h2 = bf16f(v2), h3 = bf16f(v3);
            const int r = m0 + g;
            Ah[(r * 272 + chn * 2) >> 2]       = pk2(h0, h1);
            Al[(r * 272 + chn * 2) >> 2]       = pk2(v0 - h0, v1 - h1);
            Ah[((r + 8) * 272 + chn * 2) >> 2] = pk2(h2, h3);
            Al[((r + 8) * 272 + chn * 2) >> 2] = pk2(v2 - h2, v3 - h3);
        }
    }
    if (tid < 384) sAtt[tid] = (tid < 192) ? __ldg(&as2[tid]) : __ldg(&ad2[tid - 192]);

    // ================= layer 2 =================
    gemm_layer<4>(W2, smc, sbase, tid);
    __syncthreads();
    scores_phase(smc, tid);
    __syncthreads();

#pragma unroll
    for (int p = 0; p < 4; p++)
#pragma unroll
        for (int q = 0; q < 4; q++) dA[p][q] = 0.f;

    for (int h = 0; h < 3; h++) {
        softmax_head(smc, h, tid);
        __syncthreads();
        aggregate_head(dA, smc, sbase, h, tid);
        __syncthreads();
    }

    // epilogue 2: head-mean + bias + lrelu, node-sum, atomic into sF
    {
        const int c0 = (warp >> 3) * 32;
        const int tg = lane & 3;
#pragma unroll
        for (int p = 0; p < 4; p++) {
            const int chn = c0 + 8 * p + 2 * tg;
            const float bb0 = __ldg(&b2[chn]), bb1 = __ldg(&b2[chn + 1]);
            float v0 = dA[p][0] * (1.f / 3.f) + bb0;
            float v1 = dA[p][1] * (1.f / 3.f) + bb1;
            float v2 = dA[p][2] * (1.f / 3.f) + bb0;
            float v3 = dA[p][3] * (1.f / 3.f) + bb1;
            v0 = (v0 >= 0.f) ? v0 : 0.01f * v0;
            v1 = (v1 >= 0.f) ? v1 : 0.01f * v1;
            v2 = (v2 >= 0.f) ? v2 : 0.01f * v2;
            v3 = (v3 >= 0.f) ? v3 : 0.01f * v3;
            float s0 = v0 + v2;   // column chn, two node rows
            float s1 = v1 + v3;   // column chn+1
#pragma unroll
            for (int o = 4; o < 32; o <<= 1) {
                s0 += __shfl_xor_sync(0xffffffffu, s0, o);
                s1 += __shfl_xor_sync(0xffffffffu, s1, o);
            }
            if (lane < 4) {
                atomicAdd(&sF[chn], s0);
                atomicAdd(&sF[chn + 1], s1);
            }
        }
    }
    __syncthreads();
    if (tid < 64) out[(size_t)blockIdx.x * 64 + tid] = sF[tid];
}

// ---------------------------------------------------------------------------
extern "C" void kernel_launch(void* const* d_in, const int* in_sizes, int n_in,
                              void* d_out, int out_size) {
    (void)n_in; (void)out_size;
    const float* x   = (const float*)d_in[0];
    // d_in[1] = batch_mask: equal-sized, sorted graphs -> identity layout
    const float* W1  = (const float*)d_in[2];
    const float* as1 = (const float*)d_in[3];
    const float* ad1 = (const float*)d_in[4];
    const float* b1  = (const float*)d_in[5];
    const float* W2  = (const float*)d_in[6];
    const float* as2 = (const float*)d_in[7];
    const float* ad2 = (const float*)d_in[8];
    const float* b2  = (const float*)d_in[9];
    float* out = (float*)d_out;

    const int B = in_sizes[0] / (128 * 128);

    cudaFuncSetAttribute(gat_mma_kernel,
                         cudaFuncAttributeMaxDynamicSharedMemorySize, SMEM_BYTES);
    gat_mma_kernel<<<B, 512, SMEM_BYTES>>>(x, W1, as1, ad1, b1,
                                           W2, as2, ad2, b2, out);
}